// round 8
// baseline (speedup 1.0000x reference)
#include <cuda_runtime.h>
#include <math.h>

#define F_EPS 1e-9f
#define F_INF __int_as_float(0x7f800000)

constexpr int MD  = 10;
constexpr int WPB = 8;             // trajectories per tile
constexpr int TPB = WPB * 32;      // 256 threads
constexpr int H   = 48;
constexpr int NF  = 60;
constexpr int TILES = 4;           // tiles per block (W staged once per block)

#define FULLM 0xffffffffu

__device__ __forceinline__ float mrg(float x, float y, int bit, int lane) {
    float sel = (lane & bit) ? x : y;
    float rec = __shfl_xor_sync(FULLM, sel, bit);
    return (lane & bit) ? (y + rec) : (x + rec);
}
__device__ __forceinline__ float mrgmax(float x, float y, int bit, int lane) {
    float sel = (lane & bit) ? x : y;
    float rec = __shfl_xor_sync(FULLM, sel, bit);
    return (lane & bit) ? fmaxf(y, rec) : fmaxf(x, rec);
}
__device__ __forceinline__ float solo(float x, int bit) {
    return x + __shfl_xor_sync(FULLM, x, bit);
}
__device__ __forceinline__ float solomax(float x, int bit) {
    return fmaxf(x, __shfl_xor_sync(FULLM, x, bit));
}

__device__ __forceinline__ unsigned long long pk2(float a, float b) {
    unsigned long long r;
    asm("mov.b64 %0, {%1, %2};" : "=l"(r) : "f"(a), "f"(b));
    return r;
}
__device__ __forceinline__ void upk2(unsigned long long v, float& a, float& b) {
    asm("mov.b64 {%0, %1}, %2;" : "=f"(a), "=f"(b) : "l"(v));
}
__device__ __forceinline__ unsigned long long fma2(unsigned long long a,
                                                   unsigned long long b,
                                                   unsigned long long c) {
    unsigned long long d;
    asm("fma.rn.f32x2 %0, %1, %2, %3;" : "=l"(d) : "l"(a), "l"(b), "l"(c));
    return d;
}

__global__ void __launch_bounds__(TPB)
fused_kernel(const float* __restrict__ coords, const int* __restrict__ lengths,
             const float* __restrict__ Wg, const float* __restrict__ bg,
             const float* __restrict__ lnwg, const float* __restrict__ lnbg,
             float* __restrict__ out, int B)
{
    __shared__ alignas(16) float sW[NF * H];      // 11.25 KB, staged ONCE per block
    __shared__ alignas(16) float sfT[NF * WPB];   // 1.9 KB, transposed [f][traj]
    __shared__ float sred[WPB][64];               // 2 KB

    const int tid  = threadIdx.x;
    const int w    = tid >> 5;
    const int lane = tid & 31;

    // ---- stage W once per block ----
#pragma unroll
    for (int i = tid; i < NF * H / 4; i += TPB)
        ((float4*)sW)[i] = ((const float4*)Wg)[i];

    for (int t = 0; t < TILES; t++) {
        const int t0   = (blockIdx.x * TILES + t) * WPB;
        const int traj = t0 + w;

        // =============== feature phase (per-warp, one trajectory) ===============
        if (traj < B) {
            const int   n    = lengths[traj];
            const int   m    = n - 1;
            const int   half = m >> 1;
            const float nf   = (float)n;
            const float mf   = (float)m;

            const float* cp = coords + (size_t)traj * 480;
            float r0[MD], r1[MD];
            {
                const float2* p0 = (const float2*)(cp + lane * MD);
#pragma unroll
                for (int k = 0; k < 5; k++) { float2 v = p0[k]; r0[2*k] = v.x; r0[2*k+1] = v.y; }
            }
#pragma unroll
            for (int k = 0; k < MD; k++) r1[k] = 0.f;
            if (lane < 16) {
                const float2* p1 = (const float2*)(cp + (lane + 32) * MD);
#pragma unroll
                for (int k = 0; k < 5; k++) { float2 v = p1[k]; r1[2*k] = v.x; r1[2*k+1] = v.y; }
            } else if (lane == 31) {
                const float2* p1 = (const float2*)(cp + 32 * MD);
#pragma unroll
                for (int k = 0; k < 5; k++) { float2 v = p1[k]; r1[2*k] = v.x; r1[2*k+1] = v.y; }
            }

            float csum = 0.f, cssum = 0.f;
            if (lane < n) {
#pragma unroll
                for (int k = 0; k < MD; k++) { csum += r0[k]; cssum += r0[k] * r0[k]; }
            }
            if (lane + 32 < n) {
#pragma unroll
                for (int k = 0; k < MD; k++) { csum += r1[k]; cssum += r1[k] * r1[k]; }
            }

            const bool hiLast = (n > 32);
            const int  owner  = hiLast ? (n - 33) : (n - 1);
            float tdp_l = 0.f;
#pragma unroll
            for (int k = 0; k < MD; k++) {
                float f0 = __shfl_sync(FULLM, r0[k], 0);
                float lst = hiLast ? r1[k] : r0[k];
                float dd = lst - f0;
                tdp_l += dd * dd;
            }
            float tdp_s = (lane == owner) ? tdp_l : 0.f;

            const bool v0 = lane < m;
            const bool v1 = lane + 32 < m;
            float d0[MD], d1[MD];
            float ss0 = 0.f, ss1 = 0.f;
#pragma unroll
            for (int k = 0; k < MD; k++) {
                float nx0 = __shfl_down_sync(FULLM, r0[k], 1);
                if (lane == 31) nx0 = r1[k];
                float nx1 = __shfl_down_sync(FULLM, r1[k], 1);
                float a = v0 ? (nx0 - r0[k]) : 0.f;
                float b = v1 ? (nx1 - r1[k]) : 0.f;
                d0[k] = a; d1[k] = b;
                ss0 += a * a; ss1 += b * b;
            }
            float dmag0 = (ss0 > 0.f) ? sqrtf(fmaxf(ss0, 1e-30f)) : 0.f;
            float dmag1 = (ss1 > 0.f) ? sqrtf(fmaxf(ss1, 1e-30f)) : 0.f;
            float na0 = fmaxf(dmag0, 1e-8f), na1 = fmaxf(dmag1, 1e-8f);
            float rin0 = 1.0f / na0, rin1 = 1.0f / na1;

            float fsum  = (lane < half + 1) ? dmag0 : 0.f;
            float shsum = ((lane >= half) && v0 ? dmag0 : 0.f) + dmag1;
            float dmsq  = ss0 + ss1;
            float maxdm = fmaxf(v0 ? dmag0 : -F_INF, v1 ? dmag1 : -F_INF);
            float dhalf = __shfl_sync(FULLM, dmag0, half);

            float us[MD], uss = 0.f;
#pragma unroll
            for (int k = 0; k < MD; k++) {
                float u0 = d0[k] * rin0, u1 = d1[k] * rin1;
                us[k] = u0 + u1;
                uss += u0 * u0 + u1 * u1;
            }

            // lane 31 builds delta-32 locally (rows 32,33 from GMEM)
            float rin32 = 0.f;
            if (lane == 31) {
                const float2* p2 = (const float2*)(cp + 33 * MD);
                float ssl = 0.f;
#pragma unroll
                for (int k = 0; k < 5; k++) {
                    float2 v = p2[k];
                    float a = v.x - r1[2*k];
                    float b = v.y - r1[2*k+1];
                    d1[2*k] = a; d1[2*k+1] = b;
                    ssl += a * a + b * b;
                }
                float dm = (ssl > 0.f) ? sqrtf(fmaxf(ssl, 1e-30f)) : 0.f;
                rin32 = 1.0f / fmaxf(dm, 1e-8f);
            }

            float dot0 = 0.f, dot1 = 0.f;
#pragma unroll
            for (int k = 0; k < MD; k++) {
                float dn0 = __shfl_down_sync(FULLM, d0[k], 1);
                if (lane == 31) dn0 = d1[k];
                float dn1 = __shfl_down_sync(FULLM, d1[k], 1);
                dot0 += d0[k] * dn0;
                dot1 += d1[k] * dn1;
            }
            float rinn0 = __shfl_down_sync(FULLM, rin0, 1);
            if (lane == 31) rinn0 = rin32;
            float rinn1 = __shfl_down_sync(FULLM, rin1, 1);
            float cos0 = dot0 * rin0 * rinn0;
            float cos1 = dot1 * rin1 * rinn1;
            const bool c0 = lane < n - 2;
            const bool c1 = lane + 32 < n - 2;

            float cossum = (c0 ? cos0 : 0.f) + (c1 ? cos1 : 0.f);
            float cossq  = (c0 ? cos0 * cos0 : 0.f) + (c1 ? cos1 * cos1 : 0.f);
            float negmn  = fmaxf(c0 ? -cos0 : -F_INF, c1 ? -cos1 : -F_INF);
            float maxcs  = fmaxf(c0 ? cos0 : -F_INF, c1 ? cos1 : -F_INF);
            float dirch  = ((c0 && cos0 < 0.f) ? 1.f : 0.f) + ((c1 && cos1 < 0.f) ? 1.f : 0.f);

            if (lane < 3) {
#pragma unroll
                for (int k = 0; k < MD; k++) sfT[(21 + lane * MD + k) * WPB + w] = d0[k];
            }
            if (lane < 9) sfT[(51 + lane) * WPB + w] = c0 ? (1.0f - cos0) : 0.f;

            float m0 = mrg(fsum,  shsum, 16, lane);
            float m1 = mrg(dmsq,  uss,   16, lane);
            float m2 = mrg(cossum,cossq, 16, lane);
            float m3 = mrg(dirch, csum,  16, lane);
            float m4 = mrg(cssum, tdp_s, 16, lane);
            float m5 = mrg(us[0], us[1], 16, lane);
            float m6 = mrg(us[2], us[3], 16, lane);
            float m7 = mrg(us[4], us[5], 16, lane);
            float m8 = mrg(us[6], us[7], 16, lane);
            float m9 = mrg(us[8], us[9], 16, lane);
            float n0 = mrg(m0, m1, 8, lane);
            float n1 = mrg(m2, m3, 8, lane);
            float n2 = mrg(m4, m5, 8, lane);
            float n3 = mrg(m6, m7, 8, lane);
            float n4 = mrg(m8, m9, 8, lane);
            float p0 = mrg(n0, n1, 4, lane);
            float p1 = mrg(n2, n3, 4, lane);
            n4 = solo(n4, 4);
            float q0 = mrg(p0, p1, 2, lane);
            n4 = solo(n4, 2);
            float rr = mrg(q0, n4, 1, lane);

            float tt = mrgmax(maxdm, maxcs, 16, lane);
            float uu = solomax(negmn, 16);
            tt = mrgmax(tt, uu, 8, lane);
            tt = solomax(tt, 4); tt = solomax(tt, 2); tt = solomax(tt, 1);

            sred[w][lane]      = rr;
            sred[w][32 + lane] = tt;
            __syncwarp();

            if (lane == 0) {
                const float* sr = sred[w];
                float s_fsum  = sr[0],  s_shsum = sr[16], s_dmsq = sr[8],  s_uss = sr[24];
                float s_cossum= sr[4],  s_cossq = sr[20], s_dirch= sr[12];
                float s_csum  = sr[28], s_cssum = sr[2],  s_tdp  = sr[18];
                float nsq = sr[10]*sr[10] + sr[26]*sr[26] + sr[6]*sr[6] + sr[22]*sr[22]
                          + sr[14]*sr[14] + sr[30]*sr[30] + sr[1]*sr[1] + sr[17]*sr[17]
                          + sr[9]*sr[9]   + sr[25]*sr[25];
                float s_maxdm = sr[32], s_maxcs = sr[48], s_mincs = -sr[40];

                float path = s_fsum + s_shsum - dhalf;
                float total_disp = (s_tdp > 0.f) ? sqrtf(fmaxf(s_tdp, 1e-30f)) : 0.f;
                float disp_ratio = __fdividef(total_disp, path + F_EPS);
                float loop_score = 1.f - disp_ratio;
                float ncf  = (float)(n - 2);
                float rncf = __fdividef(1.f, ncf);
                float mean_cos  = s_cossum * rncf;
                float mean_curv = 1.f - mean_cos;
                float max_curv  = 1.0f - s_mincs;
                float cvsq      = ncf - 2.0f * s_cossum + s_cossq;
                float curv_var  = (cvsq - ncf * mean_curv * mean_curv)
                                  * __fdividef(1.f, fmaxf(ncf - 1.f, 1.f));
                float std_curv  = (ncf > 1.f) ? sqrtf(fmaxf(curv_var, 1e-30f)) : 0.f;
                float curv_range = s_maxcs - s_mincs;
                float dir_chg   = s_dirch * rncf;
                float fh = s_fsum  * __fdividef(1.f, (float)(half + 1));
                float sh = s_shsum * __fdividef(1.f, (float)(m - half));
                float conv = __fdividef(fh - sh, fh + F_EPS);
                float casc = -conv;
                float npairs = mf * (mf - 1.f) * 0.5f;
                float par = 0.5f * (nsq - s_uss) * __fdividef(1.f, fmaxf(npairs, 1.f));
                float rmf = __fdividef(1.f, mf);
                float mean_dm = path * rmf;
                float dm_var  = (s_dmsq - mf * mean_dm * mean_dm)
                                * __fdividef(1.f, fmaxf(mf - 1.f, 1.f));
                float std_dm  = sqrtf(fmaxf(dm_var, 1e-30f));
                float jump = (mean_dm > F_EPS) ? __fdividef(s_maxdm, mean_dm) : 1.f;
                float cnt  = nf * (float)MD;
                float mc   = s_csum * __fdividef(1.f, cnt);
                float cvar = (s_cssum - cnt * mc * mc) * __fdividef(1.f, cnt - 1.f);
                float stdc = sqrtf(fmaxf(cvar, 1e-30f));

                sfT[0*WPB+w]  = total_disp;  sfT[1*WPB+w]  = path;
                sfT[2*WPB+w]  = disp_ratio;  sfT[3*WPB+w]  = nf * 0.1f;
                sfT[4*WPB+w]  = mean_curv;   sfT[5*WPB+w]  = max_curv;
                sfT[6*WPB+w]  = std_curv;    sfT[7*WPB+w]  = curv_range;
                sfT[8*WPB+w]  = mean_cos;    sfT[9*WPB+w]  = s_mincs;
                sfT[10*WPB+w] = dir_chg;     sfT[11*WPB+w] = disp_ratio;
                sfT[12*WPB+w] = loop_score;  sfT[13*WPB+w] = conv;
                sfT[14*WPB+w] = par;         sfT[15*WPB+w] = jump;
                sfT[16*WPB+w] = casc;        sfT[17*WPB+w] = mean_dm;
                sfT[18*WPB+w] = std_dm;      sfT[19*WPB+w] = mc;
                sfT[20*WPB+w] = stdc;
            }
        }
        __syncthreads();

        // =============== GEMM + LN + GELU phase (warps 0-1) ===============
        if (w < 2) {
            const int colg = lane & 7;               // column group (6 cols)
            const int rrow = (lane >> 3) + (w << 2); // block-row 0..7
            const int colb = colg * 6;
            const int trow = t0 + rrow;

            unsigned long long acc0, acc1, acc2;
            {
                float2 bb0 = __ldg((const float2*)(bg + colb));
                float2 bb1 = __ldg((const float2*)(bg + colb + 2));
                float2 bb2 = __ldg((const float2*)(bg + colb + 4));
                acc0 = pk2(bb0.x, bb0.y);
                acc1 = pk2(bb1.x, bb1.y);
                acc2 = pk2(bb2.x, bb2.y);
            }

#pragma unroll 10
            for (int f = 0; f < NF; f++) {
                float fv = sfT[f * WPB + rrow];
                unsigned long long fp = pk2(fv, fv);
                unsigned long long w0 = *(const unsigned long long*)(sW + f * H + colb);
                unsigned long long w1 = *(const unsigned long long*)(sW + f * H + colb + 2);
                unsigned long long w2 = *(const unsigned long long*)(sW + f * H + colb + 4);
                acc0 = fma2(fp, w0, acc0);
                acc1 = fma2(fp, w1, acc1);
                acc2 = fma2(fp, w2, acc2);
            }

            float x[6];
            upk2(acc0, x[0], x[1]);
            upk2(acc1, x[2], x[3]);
            upk2(acc2, x[4], x[5]);
            float s = 0.f, sq = 0.f;
#pragma unroll
            for (int c = 0; c < 6; c++) { s += x[c]; sq += x[c] * x[c]; }
#pragma unroll
            for (int o = 1; o < 8; o <<= 1) {
                s  += __shfl_xor_sync(FULLM, s,  o);
                sq += __shfl_xor_sync(FULLM, sq, o);
            }
            float mu  = s * (1.0f / 48.0f);
            float var = sq * (1.0f / 48.0f) - mu * mu;
            float inv = rsqrtf(var + 1e-5f);

            if (trow < B) {
                float2 a0 = __ldg((const float2*)(lnwg + colb));
                float2 a1 = __ldg((const float2*)(lnwg + colb + 2));
                float2 a2 = __ldg((const float2*)(lnwg + colb + 4));
                float2 c0 = __ldg((const float2*)(lnbg + colb));
                float2 c1 = __ldg((const float2*)(lnbg + colb + 2));
                float2 c2 = __ldg((const float2*)(lnbg + colb + 4));
                float lw[6] = {a0.x, a0.y, a1.x, a1.y, a2.x, a2.y};
                float lb[6] = {c0.x, c0.y, c1.x, c1.y, c2.x, c2.y};
                float y[6];
#pragma unroll
                for (int c = 0; c < 6; c++) {
                    float v = (x[c] - mu) * inv * lw[c] + lb[c];
                    y[c] = v * normcdff(v);       // exact GELU
                }
                float* op = out + (size_t)trow * H + colb;
                *(float2*)(op + 0) = make_float2(y[0], y[1]);
                *(float2*)(op + 2) = make_float2(y[2], y[3]);
                *(float2*)(op + 4) = make_float2(y[4], y[5]);
            }
        }
        __syncthreads();
    }
}

extern "C" void kernel_launch(void* const* d_in, const int* in_sizes, int n_in,
                              void* d_out, int out_size) {
    const float* coords  = (const float*)d_in[0];
    const int*   lengths = (const int*)d_in[1];
    const float* W       = (const float*)d_in[2];
    const float* b       = (const float*)d_in[3];
    const float* lnw     = (const float*)d_in[4];
    const float* lnb     = (const float*)d_in[5];
    float* out = (float*)d_out;

    int B = in_sizes[1];
    int tiles = (B + WPB - 1) / WPB;
    int grid = (tiles + TILES - 1) / TILES;
    fused_kernel<<<grid, TPB>>>(coords, lengths, W, b, lnw, lnb, out, B);
}

// round 9
// speedup vs baseline: 1.6949x; 1.6949x over previous
#include <cuda_runtime.h>
#include <math.h>

#define F_EPS 1e-9f
#define F_INF __int_as_float(0x7f800000)

constexpr int MD  = 10;
constexpr int H   = 48;
constexpr int NF  = 60;
constexpr int CS  = 82;            // chunk smem stride per trajectory (floats)

#define FULLM 0xffffffffu

__device__ __forceinline__ unsigned long long pk2(float a, float b) {
    unsigned long long r;
    asm("mov.b64 %0, {%1, %2};" : "=l"(r) : "f"(a), "f"(b));
    return r;
}
__device__ __forceinline__ void upk2(unsigned long long v, float& a, float& b) {
    asm("mov.b64 {%0, %1}, %2;" : "=f"(a), "=f"(b) : "l"(v));
}
__device__ __forceinline__ unsigned long long fma2(unsigned long long a,
                                                   unsigned long long b,
                                                   unsigned long long c) {
    unsigned long long d;
    asm("fma.rn.f32x2 %0, %1, %2, %3;" : "=l"(d) : "l"(a), "l"(b), "l"(c));
    return d;
}

// block = 64 threads = 2 independent warps; each warp: 32 trajectories (lane = traj)
__global__ void __launch_bounds__(64)
fused_kernel(const float* __restrict__ coords, const int* __restrict__ lengths,
             const float* __restrict__ Wg, const float* __restrict__ bg,
             const float* __restrict__ lnwg, const float* __restrict__ lnbg,
             float* __restrict__ out, int B)
{
    __shared__ alignas(16) float s_chunk[2][32 * CS];   // 2 x 10.5 KB
    __shared__ alignas(16) float s_fT[2][NF * 32];      // 2 x 7.7 KB

    const int wid  = threadIdx.x >> 5;
    const int lane = threadIdx.x & 31;
    const int t0   = (blockIdx.x * 2 + wid) * 32;
    if (t0 >= B) return;
    const int traj = t0 + lane;
    const bool vt  = traj < B;

    float* chunk = s_chunk[wid];
    float* sfT   = s_fT[wid];

    const int   n    = vt ? __ldg(lengths + traj) : 4;
    const int   m    = n - 1;
    const int   half = m >> 1;
    const float nf   = (float)n;
    const float mf   = (float)m;

    // per-lane accumulators
    float csum = 0.f, cssum = 0.f, tdp = 0.f, path = 0.f, fsum = 0.f, shsum = 0.f;
    float dmsq = 0.f, uss = 0.f, cossum = 0.f, cossq = 0.f, dirch = 0.f;
    float maxdm = -F_INF, negmn = -F_INF, maxcs = -F_INF;
    float us[MD], f0[MD], prev[MD], dprev[MD];
#pragma unroll
    for (int k = 0; k < MD; k++) { us[k] = 0.f; dprev[k] = 0.f; }
    float rinprev = 0.f;

    const float4* cb = (const float4*)coords;

    for (int c = 0; c < 6; c++) {
        // ---- stage rows [8c, 8c+8) for 32 trajectories (coalesced) ----
#pragma unroll
        for (int u = 0; u < 20; u++) {
            int j  = u * 32 + lane;          // 640 float4 per chunk
            int tt = j / 20;
            int wi = j - tt * 20;
            int g  = t0 + tt; if (g > B - 1) g = B - 1;
            float4 v = cb[(size_t)g * 120 + c * 20 + wi];
            float* dst = chunk + tt * CS + wi * 4;
            *(float2*)(dst)     = make_float2(v.x, v.y);
            *(float2*)(dst + 2) = make_float2(v.z, v.w);
        }
        __syncwarp();

        // ---- consume 8 rows serially (per-lane trajectory walk) ----
#pragma unroll
        for (int r8 = 0; r8 < 8; r8++) {
            const int r = c * 8 + r8;
            float row[MD];
            {
                const float2* rp = (const float2*)(chunk + lane * CS + r8 * MD);
#pragma unroll
                for (int k = 0; k < 5; k++) { float2 v = rp[k]; row[2*k] = v.x; row[2*k+1] = v.y; }
            }
            const bool rv = r < n;

            if (r == 0) {
#pragma unroll
                for (int k = 0; k < MD; k++) f0[k] = row[k];
            } else {
                float d[MD], ss = 0.f;
#pragma unroll
                for (int k = 0; k < MD; k++) { d[k] = row[k] - prev[k]; ss = fmaf(d[k], d[k], ss); }
                float ssc  = fmaxf(ss, 1e-30f);
                float rs   = rsqrtf(ssc);
                float dmag = (ss > 0.f) ? ssc * rs : 0.f;
                float rin  = (dmag > 1e-8f) ? rs : 1e8f;
                float cosv = 0.f;
                if (r >= 2) {
                    float dot = 0.f;
#pragma unroll
                    for (int k = 0; k < MD; k++) dot = fmaf(d[k], dprev[k], dot);
                    cosv = dot * rin * rinprev;
                }
                if (rv) {
                    const int i = r - 1;
                    path += dmag;
                    dmsq += ss;
                    if (i <= half) fsum  += dmag;
                    if (i >= half) shsum += dmag;
                    maxdm = fmaxf(maxdm, dmag);
                    uss   = fmaf(ss * rin, rin, uss);
#pragma unroll
                    for (int k = 0; k < MD; k++) us[k] = fmaf(d[k], rin, us[k]);
                    if (r >= 2) {
                        cossum += cosv;
                        cossq   = fmaf(cosv, cosv, cossq);
                        negmn   = fmaxf(negmn, -cosv);
                        maxcs   = fmaxf(maxcs, cosv);
                        if (cosv < 0.f) dirch += 1.f;
                    }
                    if (r == n - 1) {
                        float t = 0.f;
#pragma unroll
                        for (int k = 0; k < MD; k++) { float dd = row[k] - f0[k]; t = fmaf(dd, dd, t); }
                        tdp = t;
                    }
                    if (i < 3) {
#pragma unroll
                        for (int k = 0; k < MD; k++) sfT[(21 + i * MD + k) * 32 + lane] = d[k];
                    }
                }
                if (r >= 2 && r <= 10)
                    sfT[(51 + r - 2) * 32 + lane] = rv ? (1.0f - cosv) : 0.f;
#pragma unroll
                for (int k = 0; k < MD; k++) dprev[k] = d[k];
                rinprev = rin;
            }
            if (rv) {
#pragma unroll
                for (int k = 0; k < MD; k++) { csum += row[k]; cssum = fmaf(row[k], row[k], cssum); }
            }
#pragma unroll
            for (int k = 0; k < MD; k++) prev[k] = row[k];
        }
        __syncwarp();
    }

    // ---- per-lane epilogue (fully parallel, no reductions) ----
    {
        float s_mincs = -negmn;
        float total_disp = (tdp > 0.f) ? sqrtf(fmaxf(tdp, 1e-30f)) : 0.f;
        float disp_ratio = __fdividef(total_disp, path + F_EPS);
        float loop_score = 1.f - disp_ratio;
        float ncf  = (float)(n - 2);
        float rncf = __fdividef(1.f, ncf);
        float mean_cos  = cossum * rncf;
        float mean_curv = 1.f - mean_cos;
        float max_curv  = 1.0f - s_mincs;
        float cvsq      = ncf - 2.0f * cossum + cossq;
        float curv_var  = (cvsq - ncf * mean_curv * mean_curv)
                          * __fdividef(1.f, fmaxf(ncf - 1.f, 1.f));
        float std_curv  = (ncf > 1.f) ? sqrtf(fmaxf(curv_var, 1e-30f)) : 0.f;
        float curv_range = maxcs - s_mincs;
        float dir_chg   = dirch * rncf;
        float fh = fsum  * __fdividef(1.f, (float)(half + 1));
        float sh = shsum * __fdividef(1.f, (float)(m - half));
        float conv = __fdividef(fh - sh, fh + F_EPS);
        float nsq = 0.f;
#pragma unroll
        for (int k = 0; k < MD; k++) nsq = fmaf(us[k], us[k], nsq);
        float npairs = mf * (mf - 1.f) * 0.5f;
        float par = 0.5f * (nsq - uss) * __fdividef(1.f, fmaxf(npairs, 1.f));
        float mean_dm = path * __fdividef(1.f, mf);
        float dm_var  = (dmsq - mf * mean_dm * mean_dm)
                        * __fdividef(1.f, fmaxf(mf - 1.f, 1.f));
        float std_dm  = sqrtf(fmaxf(dm_var, 1e-30f));
        float jump = (mean_dm > F_EPS) ? __fdividef(maxdm, mean_dm) : 1.f;
        float cnt  = nf * (float)MD;
        float mc   = csum * __fdividef(1.f, cnt);
        float cvar = (cssum - cnt * mc * mc) * __fdividef(1.f, cnt - 1.f);
        float stdc = sqrtf(fmaxf(cvar, 1e-30f));

        sfT[ 0*32+lane] = total_disp;  sfT[ 1*32+lane] = path;
        sfT[ 2*32+lane] = disp_ratio;  sfT[ 3*32+lane] = nf * 0.1f;
        sfT[ 4*32+lane] = mean_curv;   sfT[ 5*32+lane] = max_curv;
        sfT[ 6*32+lane] = std_curv;    sfT[ 7*32+lane] = curv_range;
        sfT[ 8*32+lane] = mean_cos;    sfT[ 9*32+lane] = s_mincs;
        sfT[10*32+lane] = dir_chg;     sfT[11*32+lane] = disp_ratio;
        sfT[12*32+lane] = loop_score;  sfT[13*32+lane] = conv;
        sfT[14*32+lane] = par;         sfT[15*32+lane] = jump;
        sfT[16*32+lane] = -conv;       sfT[17*32+lane] = mean_dm;
        sfT[18*32+lane] = std_dm;      sfT[19*32+lane] = mc;
        sfT[20*32+lane] = stdc;
    }
    __syncwarp();

    // ---- GEMM + LN + GELU: lane = (rowq 0-3) x (colg 0-7); 8 rows x 6 cols each ----
    {
        const int colg = lane & 7;
        const int rowq = lane >> 3;
        const int colb = colg * 6;

        unsigned long long acc[8][3];
        {
            float2 bb0 = __ldg((const float2*)(bg + colb));
            float2 bb1 = __ldg((const float2*)(bg + colb + 2));
            float2 bb2 = __ldg((const float2*)(bg + colb + 4));
            unsigned long long b0 = pk2(bb0.x, bb0.y);
            unsigned long long b1 = pk2(bb1.x, bb1.y);
            unsigned long long b2 = pk2(bb2.x, bb2.y);
#pragma unroll
            for (int rr = 0; rr < 8; rr++) { acc[rr][0] = b0; acc[rr][1] = b1; acc[rr][2] = b2; }
        }

#pragma unroll 6
        for (int f = 0; f < NF; f++) {
            float2 wa = __ldg((const float2*)(Wg + f * H + colb));
            float2 wb = __ldg((const float2*)(Wg + f * H + colb + 2));
            float2 wc = __ldg((const float2*)(Wg + f * H + colb + 4));
            unsigned long long w0 = pk2(wa.x, wa.y);
            unsigned long long w1 = pk2(wb.x, wb.y);
            unsigned long long w2 = pk2(wc.x, wc.y);
            float4 fa = *(const float4*)(sfT + f * 32 + rowq * 8);
            float4 fb = *(const float4*)(sfT + f * 32 + rowq * 8 + 4);
            float fv[8] = {fa.x, fa.y, fa.z, fa.w, fb.x, fb.y, fb.z, fb.w};
#pragma unroll
            for (int rr = 0; rr < 8; rr++) {
                unsigned long long fp = pk2(fv[rr], fv[rr]);
                acc[rr][0] = fma2(fp, w0, acc[rr][0]);
                acc[rr][1] = fma2(fp, w1, acc[rr][1]);
                acc[rr][2] = fma2(fp, w2, acc[rr][2]);
            }
        }

        float lw[6], lb[6];
        {
            float2 a0 = __ldg((const float2*)(lnwg + colb));
            float2 a1 = __ldg((const float2*)(lnwg + colb + 2));
            float2 a2 = __ldg((const float2*)(lnwg + colb + 4));
            float2 c0 = __ldg((const float2*)(lnbg + colb));
            float2 c1 = __ldg((const float2*)(lnbg + colb + 2));
            float2 c2 = __ldg((const float2*)(lnbg + colb + 4));
            lw[0]=a0.x; lw[1]=a0.y; lw[2]=a1.x; lw[3]=a1.y; lw[4]=a2.x; lw[5]=a2.y;
            lb[0]=c0.x; lb[1]=c0.y; lb[2]=c1.x; lb[3]=c1.y; lb[4]=c2.x; lb[5]=c2.y;
        }

#pragma unroll
        for (int rr = 0; rr < 8; rr++) {
            float x[6];
            upk2(acc[rr][0], x[0], x[1]);
            upk2(acc[rr][1], x[2], x[3]);
            upk2(acc[rr][2], x[4], x[5]);
            float s = 0.f, sq = 0.f;
#pragma unroll
            for (int c = 0; c < 6; c++) { s += x[c]; sq = fmaf(x[c], x[c], sq); }
#pragma unroll
            for (int o = 1; o < 8; o <<= 1) {
                s  += __shfl_xor_sync(FULLM, s,  o);
                sq += __shfl_xor_sync(FULLM, sq, o);
            }
            float mu  = s * (1.0f / 48.0f);
            float var = sq * (1.0f / 48.0f) - mu * mu;
            float inv = rsqrtf(var + 1e-5f);

            int trow = t0 + rowq * 8 + rr;
            if (trow < B) {
                float y[6];
#pragma unroll
                for (int c = 0; c < 6; c++) {
                    float v = (x[c] - mu) * inv * lw[c] + lb[c];
                    y[c] = v * normcdff(v);     // exact GELU
                }
                float* op = out + (size_t)trow * H + colb;
                *(float2*)(op + 0) = make_float2(y[0], y[1]);
                *(float2*)(op + 2) = make_float2(y[2], y[3]);
                *(float2*)(op + 4) = make_float2(y[4], y[5]);
            }
        }
    }
}

extern "C" void kernel_launch(void* const* d_in, const int* in_sizes, int n_in,
                              void* d_out, int out_size) {
    const float* coords  = (const float*)d_in[0];
    const int*   lengths = (const int*)d_in[1];
    const float* W       = (const float*)d_in[2];
    const float* b       = (const float*)d_in[3];
    const float* lnw     = (const float*)d_in[4];
    const float* lnb     = (const float*)d_in[5];
    float* out = (float*)d_out;

    int B = in_sizes[1];
    int grid = (B + 63) / 64;
    fused_kernel<<<grid, 64>>>(coords, lengths, W, b, lnw, lnb, out, B);
}

// round 10
// speedup vs baseline: 1.9089x; 1.1262x over previous
#include <cuda_runtime.h>
#include <math.h>

#define F_EPS 1e-9f
#define F_INF __int_as_float(0x7f800000)
#define FULLM 0xffffffffu

constexpr int MD = 10;
constexpr int H  = 48;
constexpr int NF = 60;
constexpr int CS = 42;      // 4-row chunk stride (floats) per trajectory

__device__ __forceinline__ unsigned long long pk2(float a, float b) {
    unsigned long long r;
    asm("mov.b64 %0, {%1, %2};" : "=l"(r) : "f"(a), "f"(b));
    return r;
}
__device__ __forceinline__ void upk2(unsigned long long v, float& a, float& b) {
    asm("mov.b64 {%0, %1}, %2;" : "=f"(a), "=f"(b) : "l"(v));
}
__device__ __forceinline__ unsigned long long fma2(unsigned long long a,
                                                   unsigned long long b,
                                                   unsigned long long c) {
    unsigned long long d;
    asm("fma.rn.f32x2 %0, %1, %2, %3;" : "=l"(d) : "l"(a), "l"(b), "l"(c));
    return d;
}

// combine-buffer slot indices (stride 32, one column per lane)
// 0..9 us | 10 csum | 11 cssum | 12 path | 13 fsum | 14 shsum | 15 dmsq
// 16 uss | 17 cossum | 18 cossq | 19 dirch | 20 maxdm | 21 negmn | 22 maxcs
// 23 tdpA | 24..33 vA | 34..43 d23 | 44 rin23 | 45..54 d24 | 55..64 vB | 65 rin24

// block = 64 threads = one warp-PAIR handling 32 trajectories (lane = traj)
__global__ void __launch_bounds__(64)
fused_kernel(const float* __restrict__ coords, const int* __restrict__ lengths,
             const float* __restrict__ Wg, const float* __restrict__ bg,
             const float* __restrict__ lnwg, const float* __restrict__ lnbg,
             float* __restrict__ out, int B)
{
    __shared__ alignas(16) float s_chunk[2][32 * CS];   // 2 x 5.25 KB
    __shared__ alignas(16) float s_mini[32 * 10];       // row 24 for warp 0
    __shared__ alignas(16) float s_fT[NF * 32];         // 7.5 KB
    __shared__ float s_comb[66 * 32];                   // 8.25 KB

    const int h    = threadIdx.x >> 5;      // 0: rows 0-24, 1: rows 24-47
    const int lane = threadIdx.x & 31;
    const int t0   = blockIdx.x * 32;
    if (t0 >= B) return;

    const int  traj = t0 + lane;
    const bool vt   = traj < B;
    const int  n    = vt ? __ldg(lengths + traj) : 4;
    const int  m    = n - 1;
    const int  half = m >> 1;
    const float nf  = (float)n;
    const float mf  = (float)m;
    const int  base = h * 24;

    float* chunk = s_chunk[h];
    float* sfT   = s_fT;

    float csum = 0.f, cssum = 0.f, path = 0.f, fsum = 0.f, shsum = 0.f;
    float dmsq = 0.f, uss = 0.f, cossum = 0.f, cossq = 0.f, dirch = 0.f, tdpA = 0.f;
    float maxdm = -F_INF, negmn = -F_INF, maxcs = -F_INF;
    float us[MD], f0[MD], prev[MD], dprev[MD];
#pragma unroll
    for (int k = 0; k < MD; k++) { us[k] = 0.f; dprev[k] = 0.f; }
    float rinprev = 0.f;

    auto body = [&](int gr, const float* row) {
        if (gr == base) {
#pragma unroll
            for (int k = 0; k < MD; k++) f0[k] = row[k];
        } else {
            float d[MD];
            float ssa = 0.f, ssb = 0.f;
#pragma unroll
            for (int k = 0; k < 5; k++)  { d[k] = row[k] - prev[k]; ssa = fmaf(d[k], d[k], ssa); }
#pragma unroll
            for (int k = 5; k < MD; k++) { d[k] = row[k] - prev[k]; ssb = fmaf(d[k], d[k], ssb); }
            float ss   = ssa + ssb;
            float ssc  = fmaxf(ss, 1e-30f);
            float rs   = rsqrtf(ssc);
            float dmag = (ss > 0.f) ? ssc * rs : 0.f;
            float rin  = (dmag > 1e-8f) ? rs : 1e8f;
            float dot  = 0.f;
#pragma unroll
            for (int k = 0; k < MD; k++) dot = fmaf(d[k], dprev[k], dot);
            float cosv = dot * rin * rinprev;
            const bool rv = gr < n;
            if (rv) {
                const int i = gr - 1;
                path += dmag;
                dmsq += ss;
                if (i <= half) fsum  += dmag;
                if (i >= half) shsum += dmag;
                maxdm = fmaxf(maxdm, dmag);
                uss   = fmaf(ss * rin, rin, uss);
#pragma unroll
                for (int k = 0; k < MD; k++) us[k] = fmaf(d[k], rin, us[k]);
                if (gr >= base + 2) {
                    cossum += cosv;
                    cossq   = fmaf(cosv, cosv, cossq);
                    negmn   = fmaxf(negmn, -cosv);
                    maxcs   = fmaxf(maxcs, cosv);
                    if (cosv < 0.f) dirch += 1.f;
                }
                if (gr == n - 1) {
                    if (h == 0) {
                        float t = 0.f;
#pragma unroll
                        for (int k = 0; k < MD; k++) { float dd = row[k] - f0[k]; t = fmaf(dd, dd, t); }
                        tdpA = t;
                    } else {
#pragma unroll
                        for (int k = 0; k < MD; k++) s_comb[(55 + k) * 32 + lane] = row[k] - f0[k];
                    }
                }
                if (i < 3) {
#pragma unroll
                    for (int k = 0; k < MD; k++) sfT[(21 + i * MD + k) * 32 + lane] = d[k];
                }
            }
            if (gr >= 2 && gr <= 10)
                sfT[(51 + gr - 2) * 32 + lane] = rv ? (1.f - cosv) : 0.f;
            if (h == 1 && gr == 25) {
#pragma unroll
                for (int k = 0; k < MD; k++) s_comb[(45 + k) * 32 + lane] = d[k];
                s_comb[65 * 32 + lane] = rin;
            }
            if (h == 0 && gr == 24) {
#pragma unroll
                for (int k = 0; k < MD; k++) {
                    s_comb[(34 + k) * 32 + lane] = d[k];
                    s_comb[(24 + k) * 32 + lane] = row[k] - f0[k];
                }
                s_comb[44 * 32 + lane] = rin;
            }
#pragma unroll
            for (int k = 0; k < MD; k++) dprev[k] = d[k];
            rinprev = rin;
        }
        const bool own = (h == 1) || (gr < 24);   // row-level ownership (row 24 -> warp 1)
        if (gr < n && own) {
#pragma unroll
            for (int k = 0; k < MD; k++) { csum += row[k]; cssum = fmaf(row[k], row[k], cssum); }
        }
#pragma unroll
        for (int k = 0; k < MD; k++) prev[k] = row[k];
    };

    // ---- walk 24 rows in 6 chunks of 4 (coalesced staging per warp) ----
    const float4* cb4 = (const float4*)coords;
    for (int c = 0; c < 6; c++) {
#pragma unroll
        for (int u = 0; u < 10; u++) {
            int j = u * 32 + lane, tt = j / 10, wi = j - tt * 10;
            int g = t0 + tt; if (g > B - 1) g = B - 1;
            float4 v = cb4[(size_t)g * 120 + h * 60 + c * 10 + wi];
            float* dst = chunk + tt * CS + wi * 4;
            *(float2*)(dst)     = make_float2(v.x, v.y);
            *(float2*)(dst + 2) = make_float2(v.z, v.w);
        }
        __syncwarp();
#pragma unroll
        for (int r8 = 0; r8 < 4; r8++) {
            const int gr = base + c * 4 + r8;
            float row[MD];
            const float2* rp = (const float2*)(chunk + lane * CS + r8 * MD);
#pragma unroll
            for (int k = 0; k < 5; k++) { float2 v = rp[k]; row[2*k] = v.x; row[2*k+1] = v.y; }
            body(gr, row);
        }
        __syncwarp();
    }

    // ---- warp 0 extra step: row 24 (delta 23, cos 22, vA, d23) ----
    if (h == 0) {
#pragma unroll
        for (int u = 0; u < 5; u++) {
            int j = u * 32 + lane, tt = j / 5, wi = j - tt * 5;
            int g = t0 + tt; if (g > B - 1) g = B - 1;
            float2 v = ((const float2*)coords)[(size_t)g * 240 + 120 + wi];
            s_mini[tt * 10 + wi * 2]     = v.x;
            s_mini[tt * 10 + wi * 2 + 1] = v.y;
        }
        __syncwarp();
        float row[MD];
#pragma unroll
        for (int k = 0; k < MD; k++) row[k] = s_mini[lane * 10 + k];
        body(24, row);

        // publish warp-0 partials
#pragma unroll
        for (int k = 0; k < MD; k++) s_comb[k * 32 + lane] = us[k];
        s_comb[10*32+lane] = csum;   s_comb[11*32+lane] = cssum;
        s_comb[12*32+lane] = path;   s_comb[13*32+lane] = fsum;
        s_comb[14*32+lane] = shsum;  s_comb[15*32+lane] = dmsq;
        s_comb[16*32+lane] = uss;    s_comb[17*32+lane] = cossum;
        s_comb[18*32+lane] = cossq;  s_comb[19*32+lane] = dirch;
        s_comb[20*32+lane] = maxdm;  s_comb[21*32+lane] = negmn;
        s_comb[22*32+lane] = maxcs;  s_comb[23*32+lane] = tdpA;
    }
    __syncthreads();

    // ---- warp 1 merges, stitches cross terms, runs epilogue ----
    if (h == 1) {
#pragma unroll
        for (int k = 0; k < MD; k++) us[k] += s_comb[k * 32 + lane];
        csum   += s_comb[10*32+lane];  cssum  += s_comb[11*32+lane];
        path   += s_comb[12*32+lane];  fsum   += s_comb[13*32+lane];
        shsum  += s_comb[14*32+lane];  dmsq   += s_comb[15*32+lane];
        uss    += s_comb[16*32+lane];  cossum += s_comb[17*32+lane];
        cossq  += s_comb[18*32+lane];  dirch  += s_comb[19*32+lane];
        maxdm = fmaxf(maxdm, s_comb[20*32+lane]);
        negmn = fmaxf(negmn, s_comb[21*32+lane]);
        maxcs = fmaxf(maxcs, s_comb[22*32+lane]);

        float tdp;
        if (n >= 26) {
            float t = 0.f, dot = 0.f;
#pragma unroll
            for (int k = 0; k < MD; k++) {
                float dd = s_comb[(24+k)*32+lane] + s_comb[(55+k)*32+lane]; // vA + vB
                t = fmaf(dd, dd, t);
                dot = fmaf(s_comb[(34+k)*32+lane], s_comb[(45+k)*32+lane], dot); // d23.d24
            }
            tdp = t;
            float c23 = dot * s_comb[44*32+lane] * s_comb[65*32+lane];
            cossum += c23;
            cossq   = fmaf(c23, c23, cossq);
            negmn   = fmaxf(negmn, -c23);
            maxcs   = fmaxf(maxcs, c23);
            if (c23 < 0.f) dirch += 1.f;
        } else {
            tdp = s_comb[23*32+lane];
        }

        float s_mincs = -negmn;
        float total_disp = (tdp > 0.f) ? sqrtf(fmaxf(tdp, 1e-30f)) : 0.f;
        float disp_ratio = __fdividef(total_disp, path + F_EPS);
        float loop_score = 1.f - disp_ratio;
        float ncf  = (float)(n - 2);
        float rncf = __fdividef(1.f, ncf);
        float mean_cos  = cossum * rncf;
        float mean_curv = 1.f - mean_cos;
        float max_curv  = 1.0f - s_mincs;
        float cvsq      = ncf - 2.0f * cossum + cossq;
        float curv_var  = (cvsq - ncf * mean_curv * mean_curv)
                          * __fdividef(1.f, fmaxf(ncf - 1.f, 1.f));
        float std_curv  = (ncf > 1.f) ? sqrtf(fmaxf(curv_var, 1e-30f)) : 0.f;
        float curv_range = maxcs - s_mincs;
        float dir_chg   = dirch * rncf;
        float fh = fsum  * __fdividef(1.f, (float)(half + 1));
        float sh = shsum * __fdividef(1.f, (float)(m - half));
        float conv = __fdividef(fh - sh, fh + F_EPS);
        float nsq = 0.f;
#pragma unroll
        for (int k = 0; k < MD; k++) nsq = fmaf(us[k], us[k], nsq);
        float npairs = mf * (mf - 1.f) * 0.5f;
        float par = 0.5f * (nsq - uss) * __fdividef(1.f, fmaxf(npairs, 1.f));
        float mean_dm = path * __fdividef(1.f, mf);
        float dm_var  = (dmsq - mf * mean_dm * mean_dm)
                        * __fdividef(1.f, fmaxf(mf - 1.f, 1.f));
        float std_dm  = sqrtf(fmaxf(dm_var, 1e-30f));
        float jump = (mean_dm > F_EPS) ? __fdividef(maxdm, mean_dm) : 1.f;
        float cnt  = nf * (float)MD;
        float mc   = csum * __fdividef(1.f, cnt);
        float cvar = (cssum - cnt * mc * mc) * __fdividef(1.f, cnt - 1.f);
        float stdc = sqrtf(fmaxf(cvar, 1e-30f));

        sfT[ 0*32+lane] = total_disp;  sfT[ 1*32+lane] = path;
        sfT[ 2*32+lane] = disp_ratio;  sfT[ 3*32+lane] = nf * 0.1f;
        sfT[ 4*32+lane] = mean_curv;   sfT[ 5*32+lane] = max_curv;
        sfT[ 6*32+lane] = std_curv;    sfT[ 7*32+lane] = curv_range;
        sfT[ 8*32+lane] = mean_cos;    sfT[ 9*32+lane] = s_mincs;
        sfT[10*32+lane] = dir_chg;     sfT[11*32+lane] = disp_ratio;
        sfT[12*32+lane] = loop_score;  sfT[13*32+lane] = conv;
        sfT[14*32+lane] = par;         sfT[15*32+lane] = jump;
        sfT[16*32+lane] = -conv;       sfT[17*32+lane] = mean_dm;
        sfT[18*32+lane] = std_dm;      sfT[19*32+lane] = mc;
        sfT[20*32+lane] = stdc;
    }
    __syncthreads();

    // ---- GEMM + LN + GELU: warp h does 16 rows; lane = (rowq, colg), 4 rows x 6 cols ----
    {
        const int colg = lane & 7;
        const int rowq = lane >> 3;
        const int colb = colg * 6;
        const int rbase = h * 16 + rowq * 4;

        unsigned long long acc[4][3];
        {
            float2 bb0 = __ldg((const float2*)(bg + colb));
            float2 bb1 = __ldg((const float2*)(bg + colb + 2));
            float2 bb2 = __ldg((const float2*)(bg + colb + 4));
            unsigned long long b0 = pk2(bb0.x, bb0.y);
            unsigned long long b1 = pk2(bb1.x, bb1.y);
            unsigned long long b2 = pk2(bb2.x, bb2.y);
#pragma unroll
            for (int rr = 0; rr < 4; rr++) { acc[rr][0] = b0; acc[rr][1] = b1; acc[rr][2] = b2; }
        }

#pragma unroll 6
        for (int f = 0; f < NF; f++) {
            float2 wa = __ldg((const float2*)(Wg + f * H + colb));
            float2 wb = __ldg((const float2*)(Wg + f * H + colb + 2));
            float2 wc = __ldg((const float2*)(Wg + f * H + colb + 4));
            unsigned long long w0 = pk2(wa.x, wa.y);
            unsigned long long w1 = pk2(wb.x, wb.y);
            unsigned long long w2 = pk2(wc.x, wc.y);
            float4 fv = *(const float4*)(sfT + f * 32 + rbase);
            float fvv[4] = {fv.x, fv.y, fv.z, fv.w};
#pragma unroll
            for (int rr = 0; rr < 4; rr++) {
                unsigned long long fp = pk2(fvv[rr], fvv[rr]);
                acc[rr][0] = fma2(fp, w0, acc[rr][0]);
                acc[rr][1] = fma2(fp, w1, acc[rr][1]);
                acc[rr][2] = fma2(fp, w2, acc[rr][2]);
            }
        }

        float lw[6], lb[6];
        {
            float2 a0 = __ldg((const float2*)(lnwg + colb));
            float2 a1 = __ldg((const float2*)(lnwg + colb + 2));
            float2 a2 = __ldg((const float2*)(lnwg + colb + 4));
            float2 c0 = __ldg((const float2*)(lnbg + colb));
            float2 c1 = __ldg((const float2*)(lnbg + colb + 2));
            float2 c2 = __ldg((const float2*)(lnbg + colb + 4));
            lw[0]=a0.x; lw[1]=a0.y; lw[2]=a1.x; lw[3]=a1.y; lw[4]=a2.x; lw[5]=a2.y;
            lb[0]=c0.x; lb[1]=c0.y; lb[2]=c1.x; lb[3]=c1.y; lb[4]=c2.x; lb[5]=c2.y;
        }

#pragma unroll
        for (int rr = 0; rr < 4; rr++) {
            float x[6];
            upk2(acc[rr][0], x[0], x[1]);
            upk2(acc[rr][1], x[2], x[3]);
            upk2(acc[rr][2], x[4], x[5]);
            float s = 0.f, sq = 0.f;
#pragma unroll
            for (int c = 0; c < 6; c++) { s += x[c]; sq = fmaf(x[c], x[c], sq); }
#pragma unroll
            for (int o = 1; o < 8; o <<= 1) {
                s  += __shfl_xor_sync(FULLM, s,  o);
                sq += __shfl_xor_sync(FULLM, sq, o);
            }
            float mu  = s * (1.0f / 48.0f);
            float var = sq * (1.0f / 48.0f) - mu * mu;
            float inv = rsqrtf(var + 1e-5f);

            int trow = t0 + rbase + rr;
            if (trow < B) {
                float y[6];
#pragma unroll
                for (int c = 0; c < 6; c++) {
                    float v = (x[c] - mu) * inv * lw[c] + lb[c];
                    y[c] = v * normcdff(v);     // exact GELU
                }
                float* op = out + (size_t)trow * H + colb;
                *(float2*)(op + 0) = make_float2(y[0], y[1]);
                *(float2*)(op + 2) = make_float2(y[2], y[3]);
                *(float2*)(op + 4) = make_float2(y[4], y[5]);
            }
        }
    }
}

extern "C" void kernel_launch(void* const* d_in, const int* in_sizes, int n_in,
                              void* d_out, int out_size) {
    const float* coords  = (const float*)d_in[0];
    const int*   lengths = (const int*)d_in[1];
    const float* W       = (const float*)d_in[2];
    const float* b       = (const float*)d_in[3];
    const float* lnw     = (const float*)d_in[4];
    const float* lnb     = (const float*)d_in[5];
    float* out = (float*)d_out;

    int B = in_sizes[1];
    int grid = (B + 31) / 32;
    fused_kernel<<<grid, 64>>>(coords, lengths, W, b, lnw, lnb, out, B);
}